// round 4
// baseline (speedup 1.0000x reference)
#include <cuda_runtime.h>

// Problem constants
#define D_H      512
#define D_MODEL  2048
#define BB       4
#define TT       4096
#define O4       (D_MODEL / 4)     // 512 float4 columns per row

// K-split: 8 partials everywhere
#define NKM      8
#define KCM      (D_H / NKM)       // 64
#define NKV      8
#define KCV      (D_MODEL / NKV)   // 256

// Scratch (__device__ globals; no allocation allowed)
__device__ __align__(16) float g_PM [NKM * BB * D_MODEL];   // partials of mem = zH @ W_mem
__device__ __align__(16) float g_PV [NKV * BB * D_MODEL];   // partials of V   = mem @ W_v
__device__ __align__(16) float g_POV[NKV * BB * D_MODEL];   // partials of ov  = V @ W_o

// ---------------------------------------------------------------------------
// Kernel 1: mem partials. One thread per (b, o4), K-loop over 64 rows.
// grid = (16 o-chunks, 8 k-chunks) x 128 threads.  tid = b*32 + o4l.
// ---------------------------------------------------------------------------
__global__ void __launch_bounds__(128) k_mem(const float* __restrict__ zH,
                                             const float* __restrict__ Wm) {
    __shared__ float xs[BB][KCM];
    const int tid = threadIdx.x;
    const int kc  = blockIdx.y;
    for (int i = tid; i < BB * KCM; i += 128) {
        int b = i / KCM, j = i % KCM;
        xs[b][j] = zH[b * D_H + kc * KCM + j];
    }
    __syncthreads();

    const int b   = tid >> 5;
    const int o4  = blockIdx.x * 32 + (tid & 31);
    const float4* W4 = reinterpret_cast<const float4*>(Wm) + (size_t)kc * KCM * O4 + o4;
    float4 a = {0.f, 0.f, 0.f, 0.f};
    #pragma unroll 8
    for (int j = 0; j < KCM; ++j) {
        float4 w = W4[(size_t)j * O4];
        float x = xs[b][j];
        a.x += x * w.x; a.y += x * w.y; a.z += x * w.z; a.w += x * w.w;
    }
    reinterpret_cast<float4*>(g_PM)[((size_t)kc * BB + b) * O4 + o4] = a;
}

// ---------------------------------------------------------------------------
// Kernel 2: V partials. Folds the 8 PM partials in the smem staging step.
// grid = (16 o-chunks, 8 k-chunks) x 128 threads.
// ---------------------------------------------------------------------------
__global__ void __launch_bounds__(128) k_v(const float* __restrict__ Wv) {
    __shared__ float xs[BB][KCV];
    const int tid = threadIdx.x;
    const int kc  = blockIdx.y;
    for (int i = tid; i < BB * KCV; i += 128) {
        int b = i / KCV, j = i % KCV;
        int col = kc * KCV + j;
        float s = 0.f;
        #pragma unroll
        for (int p = 0; p < NKM; ++p)
            s += g_PM[((size_t)p * BB + b) * D_MODEL + col];
        xs[b][j] = s;
    }
    __syncthreads();

    const int b  = tid >> 5;
    const int o4 = blockIdx.x * 32 + (tid & 31);
    const float4* W4 = reinterpret_cast<const float4*>(Wv) + (size_t)kc * KCV * O4 + o4;
    float4 a = {0.f, 0.f, 0.f, 0.f};
    #pragma unroll 8
    for (int j = 0; j < KCV; ++j) {
        float4 w = W4[(size_t)j * O4];
        float x = xs[b][j];
        a.x += x * w.x; a.y += x * w.y; a.z += x * w.z; a.w += x * w.w;
    }
    reinterpret_cast<float4*>(g_PV)[((size_t)kc * BB + b) * O4 + o4] = a;
}

// ---------------------------------------------------------------------------
// Kernel 3: ov partials. Same shape; folds PV partials in staging.
// ---------------------------------------------------------------------------
__global__ void __launch_bounds__(128) k_ov(const float* __restrict__ Wo) {
    __shared__ float xs[BB][KCV];
    const int tid = threadIdx.x;
    const int kc  = blockIdx.y;
    for (int i = tid; i < BB * KCV; i += 128) {
        int b = i / KCV, j = i % KCV;
        int col = kc * KCV + j;
        float s = 0.f;
        #pragma unroll
        for (int p = 0; p < NKV; ++p)
            s += g_PV[((size_t)p * BB + b) * D_MODEL + col];
        xs[b][j] = s;
    }
    __syncthreads();

    const int b  = tid >> 5;
    const int o4 = blockIdx.x * 32 + (tid & 31);
    const float4* W4 = reinterpret_cast<const float4*>(Wo) + (size_t)kc * KCV * O4 + o4;
    float4 a = {0.f, 0.f, 0.f, 0.f};
    #pragma unroll 8
    for (int j = 0; j < KCV; ++j) {
        float4 w = W4[(size_t)j * O4];
        float x = xs[b][j];
        a.x += x * w.x; a.y += x * w.y; a.z += x * w.z; a.w += x * w.w;
    }
    reinterpret_cast<float4*>(g_POV)[((size_t)kc * BB + b) * O4 + o4] = a;
}

// ---------------------------------------------------------------------------
// Kernel 4: out[b,t,:] = lh[b,t,:] + sigmoid(gate) * (sum_p POV[p][b][:])
// grid = (128 t-chunks, 4 batches) x 512 threads; 32 rows/block.
// ov fold: 8 L2-hot float4 loads per thread.
// ---------------------------------------------------------------------------
#define TCHUNKS 128
#define ROWS_PER_BLOCK (TT / TCHUNKS)   // 32

__global__ void __launch_bounds__(512) k_main(const float* __restrict__ lh,
                                              const float* __restrict__ gate,
                                              float* __restrict__ out) {
    const int b  = blockIdx.y;
    const int d4 = threadIdx.x;   // 0..511 float4 column

    float4 ov = {0.f, 0.f, 0.f, 0.f};
    const float4* P4 = reinterpret_cast<const float4*>(g_POV);
    #pragma unroll
    for (int p = 0; p < NKV; ++p) {
        float4 v = P4[((size_t)p * BB + b) * O4 + d4];
        ov.x += v.x; ov.y += v.y; ov.z += v.z; ov.w += v.w;
    }
    const float g  = *gate;
    const float sg = 1.f / (1.f + expf(-g));
    ov.x *= sg; ov.y *= sg; ov.z *= sg; ov.w *= sg;

    const int t0 = blockIdx.x * ROWS_PER_BLOCK;
    const float4* LH = reinterpret_cast<const float4*>(lh);
    float4*       O  = reinterpret_cast<float4*>(out);
    size_t idx = ((size_t)b * TT + t0) * O4 + d4;

    #pragma unroll 8
    for (int tt = 0; tt < ROWS_PER_BLOCK; ++tt) {
        float4 x = __ldcs(&LH[idx]);
        x.x += ov.x; x.y += ov.y; x.z += ov.z; x.w += ov.w;
        __stcs(&O[idx], x);
        idx += O4;
    }
}

// ---------------------------------------------------------------------------
// Input order: 0 last_hidden, 1 zH, 2 W_mem, 3 W_q, 4 W_k, 5 W_v, 6 W_o, 7 gate
// ---------------------------------------------------------------------------
extern "C" void kernel_launch(void* const* d_in, const int* in_sizes, int n_in,
                              void* d_out, int out_size) {
    const float* lh   = (const float*)d_in[0];
    const float* zH   = (const float*)d_in[1];
    const float* Wm   = (const float*)d_in[2];
    const float* Wv   = (const float*)d_in[5];
    const float* Wo   = (const float*)d_in[6];
    const float* gate = (const float*)d_in[7];
    float* out = (float*)d_out;

    k_mem <<<dim3(16, NKM), 128>>>(zH, Wm);
    k_v   <<<dim3(16, NKV), 128>>>(Wv);
    k_ov  <<<dim3(16, NKV), 128>>>(Wo);
    k_main<<<dim3(TCHUNKS, BB), 512>>>(lh, gate, out);
}

// round 7
// speedup vs baseline: 1.8216x; 1.8216x over previous
#include <cuda_runtime.h>

// Problem constants
#define D_H      512
#define D_MODEL  2048
#define BB       4
#define TT       4096
#define O4       (D_MODEL / 4)     // 512 float4 columns per row

#define G        256               // grid blocks (co-resident: <= 4*148)
#define NT       256               // threads per block

#define NKM      32
#define KCM      (D_H / NKM)       // 16 rows per k-chunk (phase 1)
#define NKV      32
#define KCV      (D_MODEL / NKV)   // 64 rows per k-chunk (phases 2,3)

#define ROWS_PB  (BB * TT / G)     // 64 stream rows per block (phase 5)

// Scratch (__device__ globals; zero-init at load; no allocation allowed)
__device__ __align__(16) float g_PM [NKM * BB * D_MODEL];   // 1 MB
__device__ __align__(16) float g_PV [NKV * BB * D_MODEL];   // 1 MB
__device__ __align__(16) float g_POV[NKV * BB * D_MODEL];   // 1 MB
__device__ __align__(16) float g_OV [BB * D_MODEL];         // 32 KB
__device__ unsigned g_bar;                                  // monotonic barrier counter

// Grid barrier: monotonic counter, base captured at kernel entry (4 barriers
// per launch => counter advances by 4*G per launch; no reset needed, so it is
// graph-replay safe). All blocks are co-resident by construction.
__device__ __forceinline__ void grid_bar(unsigned base, unsigned phase) {
    __syncthreads();
    if (threadIdx.x == 0) {
        __threadfence();
        atomicAdd(&g_bar, 1u);
        const unsigned tgt = base + phase * G;
        while (atomicAdd(&g_bar, 0u) < tgt) __nanosleep(64);
        __threadfence();
    }
    __syncthreads();
}

__global__ void __launch_bounds__(NT, 4) k_fused(
    const float* __restrict__ lh,  const float* __restrict__ zH,
    const float* __restrict__ Wm,  const float* __restrict__ Wv,
    const float* __restrict__ Wo,  const float* __restrict__ gate,
    float* __restrict__ out)
{
    __shared__ float xs[BB][KCV];        // staging (phase 1 uses [BB][KCM] subset)
    __shared__ unsigned s_base;
    const int tid = threadIdx.x;
    const int bid = blockIdx.x;

    if (tid == 0)  // round down to the 4*G boundary of this launch
        s_base = (atomicAdd(&g_bar, 0u) / (4u * G)) * (4u * G);
    __syncthreads();
    const unsigned base = s_base;

    const int oc   = bid & 7;            // 8 o-chunks of 64 float4 columns
    const int kc   = bid >> 3;           // 32 k-chunks
    const int lane = tid & 63;
    const int b    = tid >> 6;
    const int o4   = oc * 64 + lane;

    // ---- Phase 1: PM[kc][b][o] = sum_{i in chunk} zH[b,i] * W_mem[i,o] ----
    if (tid < BB * KCM) {                // 64 staged values
        int bb = tid >> 4, j = tid & 15;
        xs[bb][j] = zH[bb * D_H + kc * KCM + j];
    }
    __syncthreads();
    {
        const float4* W4 = reinterpret_cast<const float4*>(Wm)
                         + (size_t)(kc * KCM) * O4 + o4;
        float4 a = {0.f, 0.f, 0.f, 0.f};
        #pragma unroll
        for (int j = 0; j < KCM; ++j) {
            float4 w = W4[(size_t)j * O4];
            float  x = xs[b][j];
            a.x += x * w.x; a.y += x * w.y; a.z += x * w.z; a.w += x * w.w;
        }
        reinterpret_cast<float4*>(g_PM)[((size_t)kc * BB + b) * O4 + o4] = a;
    }
    grid_bar(base, 1);

    // ---- Phase 2: PV[kc][b][o] = sum_{i in chunk} mem[b,i] * W_v[i,o] ----
    {   // fold the 32 PM partials while staging (L2-hot)
        int bb = tid >> 6, j = tid & 63;           // one entry per thread
        int col = kc * KCV + j;
        float s = 0.f;
        #pragma unroll
        for (int p = 0; p < NKM; ++p)
            s += g_PM[((size_t)p * BB + bb) * D_MODEL + col];
        xs[bb][j] = s;
    }
    __syncthreads();
    {
        const float4* W4 = reinterpret_cast<const float4*>(Wv)
                         + (size_t)(kc * KCV) * O4 + o4;
        float4 a = {0.f, 0.f, 0.f, 0.f};
        #pragma unroll 16
        for (int j = 0; j < KCV; ++j) {
            float4 w = W4[(size_t)j * O4];
            float  x = xs[b][j];
            a.x += x * w.x; a.y += x * w.y; a.z += x * w.z; a.w += x * w.w;
        }
        reinterpret_cast<float4*>(g_PV)[((size_t)kc * BB + b) * O4 + o4] = a;
    }
    grid_bar(base, 2);

    // ---- Phase 3: POV[kc][b][o] = sum_{i in chunk} V[b,i] * W_o[i,o] ----
    {
        int bb = tid >> 6, j = tid & 63;
        int col = kc * KCV + j;
        float s = 0.f;
        #pragma unroll
        for (int p = 0; p < NKV; ++p)
            s += g_PV[((size_t)p * BB + bb) * D_MODEL + col];
        xs[bb][j] = s;
    }
    __syncthreads();
    {
        const float4* W4 = reinterpret_cast<const float4*>(Wo)
                         + (size_t)(kc * KCV) * O4 + o4;
        float4 a = {0.f, 0.f, 0.f, 0.f};
        #pragma unroll 16
        for (int j = 0; j < KCV; ++j) {
            float4 w = W4[(size_t)j * O4];
            float  x = xs[b][j];
            a.x += x * w.x; a.y += x * w.y; a.z += x * w.z; a.w += x * w.w;
        }
        reinterpret_cast<float4*>(g_POV)[((size_t)kc * BB + b) * O4 + o4] = a;
    }
    grid_bar(base, 3);

    // ---- Phase 4: g_OV = sigmoid(gate) * sum_p POV[p]  (8192 outputs) ----
    if (bid < 32) {
        int e  = bid * NT + tid;
        int bb = e >> 11;
        int o  = e & (D_MODEL - 1);
        float s = 0.f;
        #pragma unroll
        for (int p = 0; p < NKV; ++p)
            s += g_POV[((size_t)p * BB + bb) * D_MODEL + o];
        const float gv = *gate;
        g_OV[e] = s * (1.f / (1.f + expf(-gv)));
    }
    grid_bar(base, 4);

    // ---- Phase 5: out[b,t,:] = lh[b,t,:] + g_OV[b,:]  (268 MB stream) ----
    {
        const int r0 = bid * ROWS_PB;            // 64 rows, all in one batch
        const int sb = r0 >> 12;                 // batch of this block
        const float4* OVR = reinterpret_cast<const float4*>(g_OV) + sb * O4;
        const float4 ov0 = OVR[tid];
        const float4 ov1 = OVR[tid + NT];

        const float4* LH = reinterpret_cast<const float4*>(lh);
        float4*       O  = reinterpret_cast<float4*>(out);
        size_t idx = (size_t)r0 * O4 + tid;

        #pragma unroll 4
        for (int r = 0; r < ROWS_PB; ++r) {
            float4 x0 = LH[idx];
            float4 x1 = LH[idx + NT];
            x0.x += ov0.x; x0.y += ov0.y; x0.z += ov0.z; x0.w += ov0.w;
            x1.x += ov1.x; x1.y += ov1.y; x1.z += ov1.z; x1.w += ov1.w;
            O[idx]      = x0;
            O[idx + NT] = x1;
            idx += O4;
        }
    }
}

// ---------------------------------------------------------------------------
// Input order: 0 last_hidden, 1 zH, 2 W_mem, 3 W_q, 4 W_k, 5 W_v, 6 W_o, 7 gate
// ---------------------------------------------------------------------------
extern "C" void kernel_launch(void* const* d_in, const int* in_sizes, int n_in,
                              void* d_out, int out_size) {
    const float* lh   = (const float*)d_in[0];
    const float* zH   = (const float*)d_in[1];
    const float* Wm   = (const float*)d_in[2];
    const float* Wv   = (const float*)d_in[5];
    const float* Wo   = (const float*)d_in[6];
    const float* gate = (const float*)d_in[7];
    float* out = (float*)d_out;

    k_fused<<<G, NT>>>(lh, zH, Wm, Wv, Wo, gate, out);
}